// round 13
// baseline (speedup 1.0000x reference)
#include <cuda_runtime.h>

typedef unsigned int u32;
typedef unsigned long long u64;

namespace {
constexpr int B_     = 2;
constexpr int N_     = 8192;
constexpr int KNN    = 10;
constexpr int KP1    = 11;
constexpr int SPLIT  = 8;
constexpr int QPB    = 128;
constexpr int THREADS = QPB * SPLIT;          // 1024
constexpr int SUBLEN  = N_ / SPLIT;           // 1024 (512 pairs/thread)
constexpr int GROUP   = 16;                   // candidates per group (8 pairs)
constexpr int NGROUPS = SUBLEN / GROUP;       // 64
constexpr int WARM    = 6;                    // warm-up groups (96 candidates)
constexpr int BPB     = N_ / QPB;             // 64
constexpr int NBLOCKS = B_ * BPB;             // 128 -> 1 block/SM, 32 warps
constexpr int GTOT    = NBLOCKS * THREADS;    // 131072
constexpr int LOGCAP  = 160;
constexpr u64 STRIDEB = (u64)GTOT * 16ull;    // 2MB = 2^21 (16B pair entries)
constexpr int SMEM_BYTES = N_ * 16;           // 128KB point staging (reused later)
}

__device__ float g_partials[NBLOCKS];
__device__ u32   g_arrive = 0;
__device__ uint4 g_log[(size_t)LOGCAP * GTOT];   // 320MB static scratch (legal)

__device__ __forceinline__ u64 pk2(float a, float b) {
    u64 r; asm("mov.b64 %0, {%1, %2};" : "=l"(r) : "f"(a), "f"(b)); return r;
}
__device__ __forceinline__ u64 fma2(u64 a, u64 b, u64 c) {
    u64 d; asm("fma.rn.f32x2 %0, %1, %2, %3;" : "=l"(d) : "l"(a), "l"(b), "l"(c)); return d;
}
__device__ __forceinline__ u64 add2(u64 a, u64 b) {
    u64 d; asm("add.rn.f32x2 %0, %1, %2;" : "=l"(d) : "l"(a), "l"(b)); return d;
}
__device__ __forceinline__ void unpk(u64 v, u32& lo, u32& hi) {
    asm("mov.b64 {%0, %1}, %2;" : "=r"(lo), "=r"(hi) : "l"(v));
}
__device__ __forceinline__ u32 umn(u32 a, u32 b) { return a < b ? a : b; }
__device__ __forceinline__ float uasf(u32 x) { return __uint_as_float(x); }

// Branchless float sorted-insert (keys strictly positive -> total order fine).
__device__ __forceinline__ void ins11f(float c, float (&kd)[KP1]) {
#pragma unroll
    for (int t = 0; t < KP1; ++t) {
        const float lo = fminf(c, kd[t]);
        const float hi = fmaxf(c, kd[t]);
        kd[t] = lo; c = hi;
    }
}
// u32 variant for recovery/merge (positive-float bit patterns + tags).
__device__ __forceinline__ void ins11u(u32 c, u32 (&kd)[KP1]) {
#pragma unroll
    for (int t = 0; t < KP1; ++t) {
        const u32 lo = umn(c, kd[t]);
        const u32 hi = (c > kd[t]) ? c : kd[t];
        kd[t] = lo; c = hi;
    }
}

// Predicated PAIR log: if pm < thr, store {klo, khi, jabs, jabs}, bump addr.
__device__ __forceinline__ void logpair(u64& addr, float pm, float thr,
                                        u32 klo, u32 khi, u32 jabs) {
    asm volatile(
        "{\n\t.reg .pred p;\n\t"
        "setp.lt.f32 p, %1, %2;\n\t"
        "@p st.global.v4.b32 [%0], {%3, %4, %5, %5};\n\t"
        "@p add.u64 %0, %0, %6;\n\t}"
        : "+l"(addr)
        : "f"(pm), "f"(thr), "r"(klo), "r"(khi), "r"(jabs), "l"(STRIDEB)
        : "memory");
}

__global__ __launch_bounds__(THREADS, 1)
void knn_lap_loss_kernel(const float* __restrict__ p1, const float* __restrict__ p2,
                         float* __restrict__ out) {
    extern __shared__ unsigned char smem_raw[];
    float4* buf = reinterpret_cast<float4*>(smem_raw);

    const int tid   = threadIdx.x;
    const int gtid  = blockIdx.x * THREADS + tid;
    const int b     = blockIdx.x / BPB;
    const int qbase = (blockIdx.x % BPB) * QPB;
    const float* __restrict__ p1b = p1 + (size_t)b * N_ * 3;
    const float* __restrict__ p2b = p2 + (size_t)b * N_ * 3;

    // ---- Phase 1: stage pairs: buf[2p]={x0,x1,y0,y1}, buf[2p+1]={z0,z1,w0,w1} ----
    for (int p = tid; p < N_ / 2; p += THREADS) {
        const int a = 2 * p, c = 2 * p + 1;
        float xa = p1b[a*3+0], ya = p1b[a*3+1], za = p1b[a*3+2];
        float xb = p1b[c*3+0], yb = p1b[c*3+1], zb = p1b[c*3+2];
        float wa = fmaf(xa, xa, fmaf(ya, ya, za * za));
        float wb = fmaf(xb, xb, fmaf(yb, yb, zb * zb));
        buf[2*p]   = make_float4(xa, xb, ya, yb);
        buf[2*p+1] = make_float4(za, zb, wa, wb);
    }
    __syncthreads();

    // ---- Query constants. key = dist^2 + 1 > 0 strictly. ----
    const int q   = tid & (QPB - 1);    // consecutive within warp -> LDS broadcast
    const int sub = tid >> 7;           // 0..7 (constant within warp)
    const int qi  = qbase + q;
    float qx, qy, qz, qw;
    {
        const int p = qi >> 1, h = qi & 1;
        const float4 A = buf[2*p], C = buf[2*p+1];
        qx = h ? A.y : A.x;  qy = h ? A.w : A.z;
        qz = h ? C.y : C.x;  qw = h ? C.w : C.z;
    }
    const u64 m2x2 = pk2(-2.0f*qx, -2.0f*qx);
    const u64 m2y2 = pk2(-2.0f*qy, -2.0f*qy);
    const u64 m2z2 = pk2(-2.0f*qz, -2.0f*qz);
    const float qb = qw + 1.0f;
    const u64 qb2  = pk2(qb, qb);

    float kd[KP1];
#pragma unroll
    for (int t = 0; t < KP1; ++t) kd[t] = 3.0e38f;

    u64 addr        = (u64)(g_log + gtid);
    const u64 base  = addr;
    const u64 limit = base + (u64)(LOGCAP - 8) * STRIDEB;

    const int jbeg = sub * SUBLEN;

    // ---- Phase 2a: warm-up, per-pair thr refresh + pair-min chain insert.
    // kd starts INF -> first 11 pairs always log => recovery has >= 11 keys.
    // Recall: entry holds BOTH keys; pm <= k, so k < thr => entry logged.
    for (int g = 0; g < WARM; ++g) {
        const int jg = jbeg + g * GROUP;
        const int pb = jg >> 1;
#pragma unroll
        for (int pp = 0; pp < GROUP / 2; ++pp) {
            const float4 A = buf[2*(pb+pp)], C = buf[2*(pb+pp)+1];
            u64 acc = add2(pk2(C.z, C.w), qb2);
            acc = fma2(pk2(A.x, A.y), m2x2, acc);
            acc = fma2(pk2(A.z, A.w), m2y2, acc);
            acc = fma2(pk2(C.x, C.y), m2z2, acc);
            u32 klo, khi; unpk(acc, klo, khi);
            const float pm = fminf(uasf(klo), uasf(khi));
            const float thr = (addr <= limit) ? kd[KP1-1] : 0.0f;
            logpair(addr, pm, thr, klo, khi, (u32)(jg + 2*pp));
            ins11f(pm, kd);   // pair-min chain: upper bound of true 11th -> safe
        }
    }

    // ---- Phase 2b: main scan. Per pair: 4 wide-FMA + FMNMX + predicated STG.
    // Per group of 8 pairs: fresh thr, 7-op min-tree, one chain insert. ----
    for (int g = WARM; g < NGROUPS; ++g) {
        const int jg = jbeg + g * GROUP;
        const int pb = jg >> 1;
        const float thr = (addr <= limit) ? kd[KP1-1] : 0.0f;
        float pm[GROUP / 2];
#pragma unroll
        for (int pp = 0; pp < GROUP / 2; ++pp) {
            const float4 A = buf[2*(pb+pp)], C = buf[2*(pb+pp)+1];
            u64 acc = add2(pk2(C.z, C.w), qb2);
            acc = fma2(pk2(A.x, A.y), m2x2, acc);
            acc = fma2(pk2(A.z, A.w), m2y2, acc);
            acc = fma2(pk2(C.x, C.y), m2z2, acc);
            u32 klo, khi; unpk(acc, klo, khi);
            pm[pp] = fminf(uasf(klo), uasf(khi));
            logpair(addr, pm[pp], thr, klo, khi, (u32)(jg + 2*pp));
        }
        const float m0 = fminf(fminf(pm[0], pm[1]), fminf(pm[2], pm[3]));
        const float m1 = fminf(fminf(pm[4], pm[5]), fminf(pm[6], pm[7]));
        ins11f(fminf(m0, m1), kd);
    }

    // ---- Phase 3: exact recovery. Tag = (slot<<1)|half in 9 masked key bits. ----
    const u32 cnt = (u32)((addr - base) >> 21);   // STRIDEB = 2^21
    u32 rc[KP1];
#pragma unroll
    for (int t = 0; t < KP1; ++t) rc[t] = 0xFFFFFFFFu;
    for (u32 i = 0; i < cnt; ++i) {
        const uint4 e = *reinterpret_cast<const uint4*>(base + (u64)i * STRIDEB);
        ins11u((e.x & 0xFFFFFE00u) | (i << 1) | 0u, rc);
        ins11u((e.y & 0xFFFFFE00u) | (i << 1) | 1u, rc);
    }

    __syncthreads();   // done reading staged points; smem reused below

    // ---- Phase 4: decode indices, dump sorted lists to smem ----
    u32* sval = reinterpret_cast<u32*>(smem_raw);
    u32* sidx = sval + THREADS * KP1;
    {
        const int dbase = (q * SPLIT + sub) * KP1;
#pragma unroll
        for (int r = 0; r < KP1; ++r) {
            const u32 slot = (rc[r] >> 1) & 0xFFu;
            const u32 h    = rc[r] & 1u;
            const uint4 e  = *reinterpret_cast<const uint4*>(base + (u64)slot * STRIDEB);
            sval[dbase + r] = rc[r];
            sidx[dbase + r] = e.z + h;
        }
    }
    __syncthreads();

    // ---- Phase 5: first QPB threads: 8-way tagged-union chain merge + gather ----
    float acc = 0.0f;
    if (tid < QPB) {
        u32 top[KP1];
#pragma unroll
        for (int t = 0; t < KP1; ++t) top[t] = 0xFFFFFFFFu;
#pragma unroll
        for (int l = 0; l < SPLIT; ++l) {
            const u32* vl = sval + (tid * SPLIT + l) * KP1;
#pragma unroll
            for (int r = 0; r < KP1; ++r)
                ins11u((vl[r] & 0xFFFFFF80u) | ((u32)l << 4) | (u32)r, top);
        }
        // top[0] is self (key ~ 1.0, global min) -> neighbors are top[1..10]
        float sx = 0.0f, sy = 0.0f, sz = 0.0f;
#pragma unroll
        for (int r = 1; r < KP1; ++r) {
            const u32 t = top[r];
            const int bi = (int)sidx[(tid * SPLIT + (int)((t >> 4) & 7u)) * KP1 + (int)(t & 15u)];
            sx += p1b[bi*3+0] - p2b[bi*3+0];
            sy += p1b[bi*3+1] - p2b[bi*3+1];
            sz += p1b[bi*3+2] - p2b[bi*3+2];
        }
        const int qj = qbase + tid;
        const float dqx = p1b[qj*3+0] - p2b[qj*3+0];
        const float dqy = p1b[qj*3+1] - p2b[qj*3+1];
        const float dqz = p1b[qj*3+2] - p2b[qj*3+2];
        const float inv_k = 1.0f / (float)KNN;
        acc = fabsf(fmaf(sx, inv_k, -dqx))
            + fabsf(fmaf(sy, inv_k, -dqy))
            + fabsf(fmaf(sz, inv_k, -dqz));
    }

    // ---- Phase 6: block reduction + fused deterministic final reduce ----
    float* red = reinterpret_cast<float*>(sval + 2 * THREADS * KP1);
    float* fin = red + THREADS;
    red[tid] = acc;
    __syncthreads();
#pragma unroll
    for (int s = THREADS / 2; s > 0; s >>= 1) {
        if (tid < s) red[tid] += red[tid + s];
        __syncthreads();
    }
    if (tid == 0) {
        __stcg(&g_partials[blockIdx.x], red[0]);
        __threadfence();
        const u32 prev = atomicAdd(&g_arrive, 1u);
        red[0] = (prev == (u32)(NBLOCKS - 1)) ? 1.0f : 0.0f;   // last-block flag
    }
    __syncthreads();
    if (red[0] != 0.0f) {
        if (tid < NBLOCKS) fin[tid] = __ldcg(&g_partials[tid]);
        __syncthreads();
#pragma unroll
        for (int s = NBLOCKS / 2; s > 0; s >>= 1) {
            if (tid < s) fin[tid] += fin[tid + s];
            __syncthreads();
        }
        if (tid == 0) {
            out[0] = fin[0] * (1.0f / (float)(B_ * N_ * 3));
            g_arrive = 0;   // self-reset for next graph replay
        }
    }
}

extern "C" void kernel_launch(void* const* d_in, const int* in_sizes, int n_in,
                              void* d_out, int out_size) {
    const float* p1 = (const float*)d_in[0];
    const float* p2 = (const float*)d_in[1];
    (void)in_sizes; (void)n_in; (void)out_size;

    cudaFuncSetAttribute(knn_lap_loss_kernel,
                         cudaFuncAttributeMaxDynamicSharedMemorySize, SMEM_BYTES);
    knn_lap_loss_kernel<<<NBLOCKS, THREADS, SMEM_BYTES>>>(p1, p2, (float*)d_out);
}

// round 14
// speedup vs baseline: 1.2940x; 1.2940x over previous
#include <cuda_runtime.h>

typedef unsigned int u32;
typedef unsigned long long u64;

namespace {
constexpr int B_     = 2;
constexpr int N_     = 8192;
constexpr int KNN    = 10;
constexpr int KP1    = 11;
constexpr int SPLIT  = 4;
constexpr int QPB    = 128;
constexpr int THREADS = QPB * SPLIT;          // 512
constexpr int SUBLEN  = N_ / SPLIT;           // 2048 (1024 pairs/thread)
constexpr int GROUP   = 16;                   // candidates per group (8 pairs)
constexpr int NGROUPS = SUBLEN / GROUP;       // 128
constexpr int WARM    = 6;                    // warm-up groups (96 candidates)
constexpr int BPB     = N_ / QPB;             // 64
constexpr int NBLOCKS = B_ * BPB;             // 128 -> 1 block/SM
constexpr int GTOT    = NBLOCKS * THREADS;    // 65536
constexpr int LOGCAP  = 160;
constexpr u64 STRIDEB = (u64)GTOT * 16ull;    // 1MB = 2^20 (16B pair entries)
constexpr int SMEM_BYTES = N_ * 16;           // 128KB point staging
}

__device__ float g_partials[NBLOCKS];
__device__ u32   g_arrive = 0;
__device__ uint4 g_log[(size_t)LOGCAP * GTOT];   // 160MB static scratch (legal)

__device__ __forceinline__ u64 pk2(float a, float b) {
    u64 r; asm("mov.b64 %0, {%1, %2};" : "=l"(r) : "f"(a), "f"(b)); return r;
}
__device__ __forceinline__ u64 fma2(u64 a, u64 b, u64 c) {
    u64 d; asm("fma.rn.f32x2 %0, %1, %2, %3;" : "=l"(d) : "l"(a), "l"(b), "l"(c)); return d;
}
__device__ __forceinline__ u64 add2(u64 a, u64 b) {
    u64 d; asm("add.rn.f32x2 %0, %1, %2;" : "=l"(d) : "l"(a), "l"(b)); return d;
}
__device__ __forceinline__ void unpk(u64 v, u32& lo, u32& hi) {
    asm("mov.b64 {%0, %1}, %2;" : "=r"(lo), "=r"(hi) : "l"(v));
}
__device__ __forceinline__ u32 umn(u32 a, u32 b) { return a < b ? a : b; }
__device__ __forceinline__ float uasf(u32 x) { return __uint_as_float(x); }

// Branchless 6-deep float sorted-insert (keys strictly positive).
__device__ __forceinline__ void ins6f(float c, float (&kd)[6]) {
#pragma unroll
    for (int t = 0; t < 6; ++t) {
        const float lo = fminf(c, kd[t]);
        const float hi = fmaxf(c, kd[t]);
        kd[t] = lo; c = hi;
    }
}
// u32 11-deep variant for recovery/merge (positive-float bits + tags).
__device__ __forceinline__ void ins11u(u32 c, u32 (&kd)[KP1]) {
#pragma unroll
    for (int t = 0; t < KP1; ++t) {
        const u32 lo = umn(c, kd[t]);
        const u32 hi = (c > kd[t]) ? c : kd[t];
        kd[t] = lo; c = hi;
    }
}

// Predicated PAIR log: if pm < thr, store {klo, khi, jabs, jabs}, bump addr.
__device__ __forceinline__ void logpair(u64& addr, float pm, float thr,
                                        u32 klo, u32 khi, u32 jabs) {
    asm volatile(
        "{\n\t.reg .pred p;\n\t"
        "setp.lt.f32 p, %1, %2;\n\t"
        "@p st.global.v4.b32 [%0], {%3, %4, %5, %5};\n\t"
        "@p add.u64 %0, %0, %6;\n\t}"
        : "+l"(addr)
        : "f"(pm), "f"(thr), "r"(klo), "r"(khi), "r"(jabs), "l"(STRIDEB)
        : "memory");
}

__global__ __launch_bounds__(THREADS, 1)
void knn_lap_loss_kernel(const float* __restrict__ p1, const float* __restrict__ p2,
                         float* __restrict__ out) {
    extern __shared__ unsigned char smem_raw[];
    float4* buf = reinterpret_cast<float4*>(smem_raw);

    const int tid   = threadIdx.x;
    const int gtid  = blockIdx.x * THREADS + tid;
    const int b     = blockIdx.x / BPB;
    const int qbase = (blockIdx.x % BPB) * QPB;
    const float* __restrict__ p1b = p1 + (size_t)b * N_ * 3;
    const float* __restrict__ p2b = p2 + (size_t)b * N_ * 3;

    // ---- Phase 1: stage pairs: buf[2p]={x0,x1,y0,y1}, buf[2p+1]={z0,z1,w0,w1} ----
    for (int p = tid; p < N_ / 2; p += THREADS) {
        const int a = 2 * p, c = 2 * p + 1;
        float xa = p1b[a*3+0], ya = p1b[a*3+1], za = p1b[a*3+2];
        float xb = p1b[c*3+0], yb = p1b[c*3+1], zb = p1b[c*3+2];
        float wa = fmaf(xa, xa, fmaf(ya, ya, za * za));
        float wb = fmaf(xb, xb, fmaf(yb, yb, zb * zb));
        buf[2*p]   = make_float4(xa, xb, ya, yb);
        buf[2*p+1] = make_float4(za, zb, wa, wb);
    }
    __syncthreads();

    // ---- Query constants. key = dist^2 + 1 > 0 strictly. ----
    const int q   = tid & (QPB - 1);    // consecutive within warp -> LDS broadcast
    const int sub = tid >> 7;           // 0..3 (constant within warp)
    const int qi  = qbase + q;
    float qx, qy, qz, qw;
    {
        const int p = qi >> 1, h = qi & 1;
        const float4 A = buf[2*p], C = buf[2*p+1];
        qx = h ? A.y : A.x;  qy = h ? A.w : A.z;
        qz = h ? C.y : C.x;  qw = h ? C.w : C.z;
    }
    const u64 m2x2 = pk2(-2.0f*qx, -2.0f*qx);
    const u64 m2y2 = pk2(-2.0f*qy, -2.0f*qy);
    const u64 m2z2 = pk2(-2.0f*qz, -2.0f*qz);
    const float qb = qw + 1.0f;
    const u64 qb2  = pk2(qb, qb);

    // Dual 6-deep oracle chains. thr = max(A[5],B[5]) bounds the true 11th:
    // >=6 distinct sample-groups have min <= A[5] (distinct keys), +6 from B
    // => >=12 distinct keys <= thr => true 11th <= thr. Recall-safe.
    float kdA[6], kdB[6];
#pragma unroll
    for (int t = 0; t < 6; ++t) { kdA[t] = 3.0e38f; kdB[t] = 3.0e38f; }

    u64 addr        = (u64)(g_log + gtid);
    const u64 base  = addr;
    const u64 limit = base + (u64)(LOGCAP - 8) * STRIDEB;

    const int jbeg = sub * SUBLEN;

    // ---- Phase 2a: warm-up, per-pair fresh thr + alternating chain inserts.
    // thr stays INF until both chains hold 6 reals (12 pairs) => >=12 entries
    // logged => recovery has >= 24 keys. ----
    for (int g = 0; g < WARM; ++g) {
        const int jg = jbeg + g * GROUP;
        const int pb = jg >> 1;
#pragma unroll
        for (int pp = 0; pp < GROUP / 2; ++pp) {
            const float4 A = buf[2*(pb+pp)], C = buf[2*(pb+pp)+1];
            u64 acc = add2(pk2(C.z, C.w), qb2);
            acc = fma2(pk2(A.x, A.y), m2x2, acc);
            acc = fma2(pk2(A.z, A.w), m2y2, acc);
            acc = fma2(pk2(C.x, C.y), m2z2, acc);
            u32 klo, khi; unpk(acc, klo, khi);
            const float pm = fminf(uasf(klo), uasf(khi));
            const float thr = (addr <= limit) ? fmaxf(kdA[5], kdB[5]) : 0.0f;
            logpair(addr, pm, thr, klo, khi, (u32)(jg + 2*pp));
            if (pp & 1) ins6f(pm, kdB); else ins6f(pm, kdA);
        }
    }

    // ---- Phase 2b: main scan. thr is STALE BY ONE GROUP: read chain state
    // before this group's inserts -> insert chains are off the critical path. ----
    float thr_cur = fmaxf(kdA[5], kdB[5]);
    for (int g = WARM; g < NGROUPS; ++g) {
        const int jg = jbeg + g * GROUP;
        const int pb = jg >> 1;
        const float thr = (addr <= limit) ? thr_cur : 0.0f;
        float pm[GROUP / 2];
#pragma unroll
        for (int pp = 0; pp < GROUP / 2; ++pp) {
            const float4 A = buf[2*(pb+pp)], C = buf[2*(pb+pp)+1];
            u64 acc = add2(pk2(C.z, C.w), qb2);
            acc = fma2(pk2(A.x, A.y), m2x2, acc);
            acc = fma2(pk2(A.z, A.w), m2y2, acc);
            acc = fma2(pk2(C.x, C.y), m2z2, acc);
            u32 klo, khi; unpk(acc, klo, khi);
            pm[pp] = fminf(uasf(klo), uasf(khi));
            logpair(addr, pm[pp], thr, klo, khi, (u32)(jg + 2*pp));
        }
        // Read BEFORE inserts -> next group's thr depends on g-1's inserts only.
        thr_cur = fmaxf(kdA[5], kdB[5]);
        const float mA = fminf(fminf(pm[0], pm[1]), fminf(pm[2], pm[3]));
        const float mB = fminf(fminf(pm[4], pm[5]), fminf(pm[6], pm[7]));
        ins6f(mA, kdA);           // two independent 24-cyc chains
        ins6f(mB, kdB);
    }

    // ---- Phase 3: exact recovery. Tag = (slot<<1)|half in 9 masked key bits. ----
    const u32 cnt = (u32)((addr - base) >> 20);   // STRIDEB = 2^20
    u32 rc[KP1];
#pragma unroll
    for (int t = 0; t < KP1; ++t) rc[t] = 0xFFFFFFFFu;
    for (u32 i = 0; i < cnt; ++i) {
        const uint4 e = *reinterpret_cast<const uint4*>(base + (u64)i * STRIDEB);
        ins11u((e.x & 0xFFFFFE00u) | (i << 1) | 0u, rc);
        ins11u((e.y & 0xFFFFFE00u) | (i << 1) | 1u, rc);
    }

    __syncthreads();   // done reading staged points; smem reused below

    // ---- Phase 4: decode indices, dump sorted lists to smem ----
    u32* sval = reinterpret_cast<u32*>(smem_raw);
    u32* sidx = sval + THREADS * KP1;
    {
        const int dbase = (q * SPLIT + sub) * KP1;
#pragma unroll
        for (int r = 0; r < KP1; ++r) {
            const u32 slot = (rc[r] >> 1) & 0xFFu;
            const u32 h    = rc[r] & 1u;
            const uint4 e  = *reinterpret_cast<const uint4*>(base + (u64)slot * STRIDEB);
            sval[dbase + r] = rc[r];
            sidx[dbase + r] = e.z + h;
        }
    }
    __syncthreads();

    // ---- Phase 5: sub==0 threads 4-way merge + gather + per-query L1 ----
    float acc = 0.0f;
    if (sub == 0) {
        const u32* v0 = sval + (q * SPLIT + 0) * KP1;
        const u32* v1 = sval + (q * SPLIT + 1) * KP1;
        const u32* v2 = sval + (q * SPLIT + 2) * KP1;
        const u32* v3 = sval + (q * SPLIT + 3) * KP1;
        const u32* i0 = sidx + (q * SPLIT + 0) * KP1;
        const u32* i1 = sidx + (q * SPLIT + 1) * KP1;
        const u32* i2 = sidx + (q * SPLIT + 2) * KP1;
        const u32* i3 = sidx + (q * SPLIT + 3) * KP1;

        int c0 = 0, c1 = 0, c2 = 0, c3 = 0;
        u32 nidx[KP1];
#pragma unroll
        for (int r = 0; r < KP1; ++r) {
            const u32 h0 = v0[c0], h1 = v1[c1], h2 = v2[c2], h3 = v3[c3];
            const u32 m = umn(umn(h0, h1), umn(h2, h3));
            u32 bi;
            if (m == h0)      { bi = i0[c0]; ++c0; }
            else if (m == h1) { bi = i1[c1]; ++c1; }
            else if (m == h2) { bi = i2[c2]; ++c2; }
            else              { bi = i3[c3]; ++c3; }
            nidx[r] = bi;
        }

        // nidx[0] is self (key = 1.0, global min) -> neighbors are nidx[1..10]
        float sx = 0.0f, sy = 0.0f, sz = 0.0f;
#pragma unroll
        for (int r = 1; r < KP1; ++r) {
            const int bi = (int)nidx[r];
            sx += p1b[bi*3+0] - p2b[bi*3+0];
            sy += p1b[bi*3+1] - p2b[bi*3+1];
            sz += p1b[bi*3+2] - p2b[bi*3+2];
        }
        const float dqx = p1b[qi*3+0] - p2b[qi*3+0];
        const float dqy = p1b[qi*3+1] - p2b[qi*3+1];
        const float dqz = p1b[qi*3+2] - p2b[qi*3+2];
        const float inv_k = 1.0f / (float)KNN;
        acc = fabsf(fmaf(sx, inv_k, -dqx))
            + fabsf(fmaf(sy, inv_k, -dqy))
            + fabsf(fmaf(sz, inv_k, -dqz));
    }

    // ---- Phase 6: block reduction + fused deterministic final reduce ----
    float* red = reinterpret_cast<float*>(sval + 2 * THREADS * KP1);
    float* fin = red + THREADS;
    red[tid] = acc;
    __syncthreads();
#pragma unroll
    for (int s = THREADS / 2; s > 0; s >>= 1) {
        if (tid < s) red[tid] += red[tid + s];
        __syncthreads();
    }
    if (tid == 0) {
        __stcg(&g_partials[blockIdx.x], red[0]);
        __threadfence();
        const u32 prev = atomicAdd(&g_arrive, 1u);
        red[0] = (prev == (u32)(NBLOCKS - 1)) ? 1.0f : 0.0f;   // last-block flag
    }
    __syncthreads();
    if (red[0] != 0.0f) {
        if (tid < NBLOCKS) fin[tid] = __ldcg(&g_partials[tid]);
        __syncthreads();
#pragma unroll
        for (int s = NBLOCKS / 2; s > 0; s >>= 1) {
            if (tid < s) fin[tid] += fin[tid + s];
            __syncthreads();
        }
        if (tid == 0) {
            out[0] = fin[0] * (1.0f / (float)(B_ * N_ * 3));
            g_arrive = 0;   // self-reset for next graph replay
        }
    }
}

extern "C" void kernel_launch(void* const* d_in, const int* in_sizes, int n_in,
                              void* d_out, int out_size) {
    const float* p1 = (const float*)d_in[0];
    const float* p2 = (const float*)d_in[1];
    (void)in_sizes; (void)n_in; (void)out_size;

    cudaFuncSetAttribute(knn_lap_loss_kernel,
                         cudaFuncAttributeMaxDynamicSharedMemorySize, SMEM_BYTES);
    knn_lap_loss_kernel<<<NBLOCKS, THREADS, SMEM_BYTES>>>(p1, p2, (float*)d_out);
}